// round 2
// baseline (speedup 1.0000x reference)
#include <cuda_runtime.h>
#include <math.h>

#define C_DIM 1000
#define ALPHA 0.01f
#define EPS_V 1e-15f
#define WARPS_PER_BLOCK 8
#define MAX_PARTIALS 16384

// Scratch: transposed T_result (4 MB) and per-block partial sums.
__device__ float g_Tt[C_DIM * C_DIM];
__device__ float g_partials[MAX_PARTIALS];

// ---------------------------------------------------------------------------
// Kernel 1: Tt[t][c] = T[c][t] + ALPHA * corr[c][t]   (tiled transpose+axpy)
// ---------------------------------------------------------------------------
__global__ void prep_T_kernel(const float* __restrict__ T,
                              const float* __restrict__ corr) {
    __shared__ float tile[32][33];
    const int t0 = blockIdx.x * 32;
    const int c0 = blockIdx.y * 32;
    const int tx = threadIdx.x;      // 0..31
    const int ty = threadIdx.y;      // 0..7

#pragma unroll
    for (int k = 0; k < 32; k += 8) {
        int c = c0 + ty + k;
        int t = t0 + tx;
        if (c < C_DIM && t < C_DIM)
            tile[ty + k][tx] = T[(size_t)c * C_DIM + t] + ALPHA * corr[(size_t)c * C_DIM + t];
    }
    __syncthreads();
#pragma unroll
    for (int k = 0; k < 32; k += 8) {
        int t = t0 + ty + k;
        int c = c0 + tx;
        if (t < C_DIM && c < C_DIM)
            g_Tt[(size_t)t * C_DIM + c] = tile[tx][ty + k];
    }
}

// ---------------------------------------------------------------------------
// Kernel 2: one warp per row. Single pass over `out` in registers.
//   m   = max(out[i,:])
//   S   = sum exp(out[i,:]-m)
//   D   = sum exp(out[i,:]-m) * Tt[t, :]
//   lse = m + log(S); ce = lse - x_t
//   pro1 = exp(x_t - m)/S; pro2 = D/S; beta = pro1/(pro2+eps)
//   contrib = beta * ce  -> block partial sum
// Row = 1000 fp32 = exactly 250 float4 (row byte-stride 4000 is 16B-aligned).
// ---------------------------------------------------------------------------
__global__ __launch_bounds__(256) void row_loss_kernel(
    const float* __restrict__ logits,
    const int* __restrict__ target,   // int32 (JAX x64-disabled)
    int B) {
    const int warp = threadIdx.x >> 5;
    const int lane = threadIdx.x & 31;
    const int row  = blockIdx.x * WARPS_PER_BLOCK + warp;

    __shared__ float wsum[WARPS_PER_BLOCK];
    float contrib = 0.0f;

    if (row < B) {
        const float4* r4 = reinterpret_cast<const float4*>(logits + (size_t)row * C_DIM);

        float4 v[8];
#pragma unroll
        for (int j = 0; j < 8; j++) {
            int i4 = lane + 32 * j;
            if (i4 < 250) {
                v[j] = __ldg(&r4[i4]);
            } else {
                v[j] = make_float4(-INFINITY, -INFINITY, -INFINITY, -INFINITY);
            }
        }

        // ---- warp max ----
        float m = -INFINITY;
#pragma unroll
        for (int j = 0; j < 8; j++)
            m = fmaxf(m, fmaxf(fmaxf(v[j].x, v[j].y), fmaxf(v[j].z, v[j].w)));
#pragma unroll
        for (int o = 16; o > 0; o >>= 1)
            m = fmaxf(m, __shfl_xor_sync(0xffffffffu, m, o));

        // ---- extract x_t = logits[row, t] via uniform shuffle ----
        int t = target[row];                       // uniform across the warp
        t = (t < 0) ? 0 : ((t >= C_DIM) ? C_DIM - 1 : t);  // defensive clamp
        const int q    = t >> 2;                  // float4 index (< 250)
        const int comp = t & 3;
        const int jt   = q >> 5;                  // which register (uniform)
        const int src  = q & 31;                  // which lane
        float4 vt;
        switch (jt) {
            case 0: vt = v[0]; break; case 1: vt = v[1]; break;
            case 2: vt = v[2]; break; case 3: vt = v[3]; break;
            case 4: vt = v[4]; break; case 5: vt = v[5]; break;
            case 6: vt = v[6]; break; default: vt = v[7]; break;
        }
        float cand = (comp == 0) ? vt.x : (comp == 1) ? vt.y : (comp == 2) ? vt.z : vt.w;
        const float x_t = __shfl_sync(0xffffffffu, cand, src);

        // ---- exp in place + sum ----  (exp(-inf - m) = 0 for padding lanes)
        float s = 0.0f;
#pragma unroll
        for (int j = 0; j < 8; j++) {
            v[j].x = __expf(v[j].x - m);
            v[j].y = __expf(v[j].y - m);
            v[j].z = __expf(v[j].z - m);
            v[j].w = __expf(v[j].w - m);
            s += (v[j].x + v[j].y) + (v[j].z + v[j].w);
        }
#pragma unroll
        for (int o = 16; o > 0; o >>= 1)
            s += __shfl_xor_sync(0xffffffffu, s, o);

        // ---- dot with Tt[t,:]  (4 KB row, L2-resident) ----
        const float4* tt4 = reinterpret_cast<const float4*>(g_Tt + (size_t)t * C_DIM);
        float d = 0.0f;
#pragma unroll
        for (int j = 0; j < 8; j++) {
            int i4 = lane + 32 * j;
            if (i4 < 250) {
                float4 tv = __ldg(&tt4[i4]);
                d += v[j].x * tv.x + v[j].y * tv.y + v[j].z * tv.z + v[j].w * tv.w;
            }
        }
#pragma unroll
        for (int o = 16; o > 0; o >>= 1)
            d += __shfl_xor_sync(0xffffffffu, d, o);

        if (lane == 0) {
            float lse  = m + logf(s);
            float ce   = lse - x_t;                 // -log_softmax[t]
            float pro1 = __expf(x_t - m) / s;       // p[t]
            float pro2 = d / s;                     // dot(p, Tt[t])
            float beta = pro1 / (pro2 + EPS_V);
            contrib = beta * ce;
        }
    }

    if (lane == 0) wsum[warp] = contrib;
    __syncthreads();

    if (threadIdx.x == 0) {
        float s = 0.0f;
#pragma unroll
        for (int w = 0; w < WARPS_PER_BLOCK; w++) s += wsum[w];
        g_partials[blockIdx.x] = s;
    }
}

// ---------------------------------------------------------------------------
// Kernel 3: deterministic final reduction of per-block partials.
// ---------------------------------------------------------------------------
__global__ void final_reduce_kernel(float* __restrict__ out, int nblocks, float invB) {
    __shared__ float sh[256];
    float s = 0.0f;
    for (int i = threadIdx.x; i < nblocks; i += 256) s += g_partials[i];
    sh[threadIdx.x] = s;
    __syncthreads();
#pragma unroll
    for (int o = 128; o > 0; o >>= 1) {
        if (threadIdx.x < o) sh[threadIdx.x] += sh[threadIdx.x + o];
        __syncthreads();
    }
    if (threadIdx.x == 0) out[0] = sh[0] * invB;
}

// ---------------------------------------------------------------------------
extern "C" void kernel_launch(void* const* d_in, const int* in_sizes, int n_in,
                              void* d_out, int out_size) {
    const float* logits = (const float*)d_in[0];      // [B, C] fp32
    const float* corr   = (const float*)d_in[1];      // [C, C] fp32
    const int*   target = (const int*)d_in[2];        // [B] int32
    const float* T      = (const float*)d_in[3];      // [C, C] fp32

    const int B = in_sizes[2];

    // 1) Tt = (T + alpha*corr)^T
    dim3 tpb(32, 8);
    dim3 grid((C_DIM + 31) / 32, (C_DIM + 31) / 32);
    prep_T_kernel<<<grid, tpb>>>(T, corr);

    // 2) per-row loss partials
    int blocks = (B + WARPS_PER_BLOCK - 1) / WARPS_PER_BLOCK;
    row_loss_kernel<<<blocks, 32 * WARPS_PER_BLOCK>>>(logits, target, B);

    // 3) deterministic mean
    final_reduce_kernel<<<1, 256>>>((float*)d_out, blocks, 1.0f / (float)B);
}